// round 2
// baseline (speedup 1.0000x reference)
#include <cuda_runtime.h>

#define NN 50000
#define EE 1600000
#define D  64

// ---- scratch (static device memory: allowed). float4 arrays => 16B alignment. ----
__device__ float4 g_hmu4[NN * 16];   // relu(mu @ W3.T)
__device__ float4 g_hmw4[NN * 16];   // g_hmu @ W4c.T
__device__ float4 g_S4  [NN * 16];   // segment-sum of hmw[dst] over src
__device__ float  g_sp [NN];         // sum relu(x[dst])
__device__ float  g_sm [NN];         // sum relu(-x[dst])
__device__ float  g_ewp[NN];         // sum relu(edge_w)
__device__ float  g_ewm[NN];         // sum relu(-edge_w)
__device__ float  g_a1[D], g_a2[D], g_b1[D], g_b2[D];

// ---- zero the accumulators (graph-replay safe) ----
__global__ void zero_kernel() {
    int i = blockIdx.x * blockDim.x + threadIdx.x;
    if (i < NN * 16) g_S4[i] = make_float4(0.f, 0.f, 0.f, 0.f);
    if (i < NN) { g_sp[i] = 0.0f; g_sm[i] = 0.0f; g_ewp[i] = 0.0f; g_ewm[i] = 0.0f; }
}

// ---- precompute the 4 collapsed vectors ----
// a1 = W4[:,0:64]   @ relu(W1);  a2 = W4[:,0:64]   @ relu(-W1)
// b1 = W4[:,64:128] @ relu(W2);  b2 = W4[:,64:128] @ relu(-W2)
__global__ void vec_kernel(const float* __restrict__ W1, const float* __restrict__ W2,
                           const float* __restrict__ W4) {
    int o2 = threadIdx.x;   // 0..63
    float a1 = 0.f, a2 = 0.f, b1 = 0.f, b2 = 0.f;
    for (int o = 0; o < D; o++) {
        float w4a = W4[o2 * 192 + o];
        float w4b = W4[o2 * 192 + 64 + o];
        float w1 = W1[o], w2 = W2[o];
        a1 = fmaf(w4a, fmaxf(w1, 0.f), a1);
        a2 = fmaf(w4a, fmaxf(-w1, 0.f), a2);
        b1 = fmaf(w4b, fmaxf(w2, 0.f), b1);
        b2 = fmaf(w4b, fmaxf(-w2, 0.f), b2);
    }
    g_a1[o2] = a1; g_a2[o2] = a2; g_b1[o2] = b1; g_b2[o2] = b2;
}

// ---- fused dual GEMM: h_mu = relu(mu@W3.T); hmw = h_mu @ W4c.T ----
// 256 threads = 16 nodes/block * 16 threads; each thread computes 4 outputs (float4).
__global__ __launch_bounds__(256) void gemm_kernel(const float* __restrict__ mu,
                                                   const float* __restrict__ W3,
                                                   const float* __restrict__ W4) {
    __shared__ float W3T[D * D];    // W3T[k*64+o] = W3[o*64+k]
    __shared__ float W4cT[D * D];   // W4cT[j*64+o] = W4[o*192+128+j]
    __shared__ float mus[16 * 68];  // padded rows (broadcast-friendly)
    __shared__ float hs [16 * 68];

    int t = threadIdx.x;
    for (int i = t; i < D * D; i += 256) {
        int o = i >> 6, k = i & 63;
        W3T [k * D + o] = W3[i];
        W4cT[k * D + o] = W4[o * 192 + 128 + k];
    }

    int g = t >> 4;        // node within block group, 0..15
    int q = t & 15;        // quarter-row, owns cols 4q..4q+3
    const float4* W3T4  = reinterpret_cast<const float4*>(W3T);
    const float4* W4cT4 = reinterpret_cast<const float4*>(W4cT);

    for (int n0 = blockIdx.x * 16; n0 < NN; n0 += gridDim.x * 16) {
        int n = n0 + g;
        __syncthreads();
        // stage mu row
        float4 mrow = reinterpret_cast<const float4*>(mu)[n * 16 + q];
        *reinterpret_cast<float4*>(&mus[g * 68 + 4 * q]) = mrow;
        __syncthreads();

        float4 acc = make_float4(0.f, 0.f, 0.f, 0.f);
        #pragma unroll
        for (int k = 0; k < D; k++) {
            float m = mus[g * 68 + k];
            float4 w = W3T4[k * 16 + q];
            acc.x = fmaf(m, w.x, acc.x); acc.y = fmaf(m, w.y, acc.y);
            acc.z = fmaf(m, w.z, acc.z); acc.w = fmaf(m, w.w, acc.w);
        }
        float4 h = make_float4(fmaxf(acc.x, 0.f), fmaxf(acc.y, 0.f),
                               fmaxf(acc.z, 0.f), fmaxf(acc.w, 0.f));
        *reinterpret_cast<float4*>(&hs[g * 68 + 4 * q]) = h;
        __syncthreads();

        float4 acc2 = make_float4(0.f, 0.f, 0.f, 0.f);
        #pragma unroll
        for (int j = 0; j < D; j++) {
            float hv = hs[g * 68 + j];
            float4 w = W4cT4[j * 16 + q];
            acc2.x = fmaf(hv, w.x, acc2.x); acc2.y = fmaf(hv, w.y, acc2.y);
            acc2.z = fmaf(hv, w.z, acc2.z); acc2.w = fmaf(hv, w.w, acc2.w);
        }
        g_hmu4[n * 16 + q] = h;
        g_hmw4[n * 16 + q] = acc2;
    }
}

// ---- edge scatter: per edge, gather hmw[dst] (64 f32) and red-add into S[src];
//      plus 4 scalar per-node sums. 2 edges per warp, float4 per lane. ----
__global__ __launch_bounds__(256) void edge_kernel(const int* __restrict__ ei,
                                                   const float* __restrict__ ew,
                                                   const float* __restrict__ x) {
    int warp = blockIdx.x * 8 + (threadIdx.x >> 5);
    int lane = threadIdx.x & 31;
    int sub  = lane >> 4;            // which of the warp's 2 edges
    int q    = lane & 15;            // quarter index: floats 4q..4q+3
    int e = warp * 2 + sub;          // grid sized exactly: e < EE

    int src = ei[e];
    int dst = ei[EE + e];

    if (q == 0) {
        float xv = x[dst];
        atomicAdd(&g_sp[src], fmaxf(xv, 0.f));
        atomicAdd(&g_sm[src], fmaxf(-xv, 0.f));
        float w = ew[e];
        atomicAdd(&g_ewp[src], fmaxf(w, 0.f));
        atomicAdd(&g_ewm[src], fmaxf(-w, 0.f));
    }

    float4 v = g_hmw4[dst * 16 + q];
    float* p = reinterpret_cast<float*>(&g_S4[src * 16 + q]);
    asm volatile("red.global.add.v4.f32 [%0], {%1,%2,%3,%4};"
                 :: "l"(p), "f"(v.x), "f"(v.y), "f"(v.z), "f"(v.w)
                 : "memory");
}

// ---- epilogue: out = relu(h_x + h_mu + relu(z)) ----
__global__ __launch_bounds__(256) void final_kernel(const float* __restrict__ x,
                                                    const float* __restrict__ W1,
                                                    float* __restrict__ out) {
    int i = blockIdx.x * blockDim.x + threadIdx.x;   // grid covers NN*64 exactly
    int n = i >> 6, o = i & 63;
    const float* S   = reinterpret_cast<const float*>(g_S4);
    const float* hmu = reinterpret_cast<const float*>(g_hmu4);
    float z = g_sp[n] * g_a1[o] + g_sm[n] * g_a2[o]
            + g_ewp[n] * g_b1[o] + g_ewm[n] * g_b2[o] + S[i];
    float hx = fmaxf(x[n] * W1[o], 0.f);
    out[i] = fmaxf(hx + hmu[i] + fmaxf(z, 0.f), 0.f);
}

extern "C" void kernel_launch(void* const* d_in, const int* in_sizes, int n_in,
                              void* d_out, int out_size) {
    const float* mu = (const float*)d_in[0];
    const float* x  = (const float*)d_in[1];
    const int*   ei = (const int*)d_in[2];
    const float* ew = (const float*)d_in[3];
    const float* W1 = (const float*)d_in[4];
    const float* W2 = (const float*)d_in[5];
    const float* W3 = (const float*)d_in[6];
    const float* W4 = (const float*)d_in[7];
    float* out = (float*)d_out;

    zero_kernel<<<(NN * D + 255) / 256, 256>>>();
    vec_kernel<<<1, 64>>>(W1, W2, W4);
    gemm_kernel<<<888, 256>>>(mu, W3, W4);
    edge_kernel<<<EE / 16, 256>>>(ei, ew, x);   // 100000 blocks, 16 edges each
    final_kernel<<<(NN * D) / 256, 256>>>(x, W1, out);
}